// round 2
// baseline (speedup 1.0000x reference)
#include <cuda_runtime.h>

#define N_NODES 100000
#define N_EDGES 1600000
#define NFEAT   128
#define NHID    64
#define NCLASS  16

// Scratch (device globals — no allocation allowed in kernel_launch)
__device__ float g_h1[N_NODES * NHID];     // X @ W1
__device__ float g_agg1[N_NODES * NHID];   // scatter1 accumulator
__device__ float g_h2[N_NODES * NCLASS];   // relu(agg1) @ W2

// ---------------- f32x2 packed-FMA helpers (SASS FFMA2 — only via PTX) ------
__device__ __forceinline__ void fma2(unsigned long long& d,
                                     unsigned long long a,
                                     unsigned long long b) {
    asm("fma.rn.f32x2 %0, %1, %2, %3;" : "=l"(d) : "l"(a), "l"(b), "l"(d));
}
__device__ __forceinline__ unsigned long long pack2(float a) {
    unsigned long long r;
    asm("mov.b64 %0, {%1, %1};" : "=l"(r) : "f"(a));
    return r;
}
__device__ __forceinline__ float2 unpack2(unsigned long long p) {
    float2 f;
    asm("mov.b64 {%0, %1}, %2;" : "=f"(f.x), "=f"(f.y) : "l"(p));
    return f;
}

// ---------------------------------------------------------------------------
// Zero agg1 and d_out (atomically accumulated; must start at 0 every launch).
// ---------------------------------------------------------------------------
__global__ void zero_kernel(float* __restrict__ out) {
    const int stride = gridDim.x * blockDim.x;
    int i = blockIdx.x * blockDim.x + threadIdx.x;
    const float4 z = make_float4(0.f, 0.f, 0.f, 0.f);
    const int n1 = N_NODES * NHID / 4;
    const int n2 = N_NODES * NCLASS / 4;
    for (int idx = i; idx < n1; idx += stride)
        reinterpret_cast<float4*>(g_agg1)[idx] = z;
    for (int idx = i; idx < n2; idx += stride)
        reinterpret_cast<float4*>(out)[idx] = z;
}

// ---------------------------------------------------------------------------
// GEMM1: g_h1[100000,64] = X[100000,128] @ W1[128,64]   (fp32, FFMA2)
// 64x64 block tile, K-chunks of 16, 256 threads, 4x4 microtile/thread.
// A staged k-duplicated in smem so (a,a) pairs load as a single LDS.64;
// B pairs come directly from LDS.128 of Ws. 8 FFMA2 per k per thread.
// ---------------------------------------------------------------------------
__global__ __launch_bounds__(256) void gemm1_kernel(const float* __restrict__ X,
                                                    const float* __restrict__ W) {
    __shared__ float Xd[64][34];   // duplicated: Xd[r][2k]=Xd[r][2k+1]=x(r,k)
    __shared__ float Ws[16][68];   // row stride 68 floats (16B aligned)

    const int tid = threadIdx.x;
    const int m0  = blockIdx.x * 64;
    const int tx  = tid & 15;        // output-col group (cols tx*4..+4)
    const int ty  = tid >> 4;        // output-row group (rows ty*4..+4)

    const int xrow  = tid >> 2;      // 0..63
    const int xcol4 = tid & 3;       // k-subgroup
    const int wrow  = tid >> 4;      // 0..15
    const int wcol4 = tid & 15;

    const int gm = m0 + xrow;
    const bool mvalid = (gm < N_NODES);

    unsigned long long acc[4][2] = {};   // 4 rows x 2 col-pairs (= 4 cols)

    for (int kc = 0; kc < NFEAT; kc += 16) {
        float4 xv = make_float4(0.f, 0.f, 0.f, 0.f);
        if (mvalid)
            xv = *reinterpret_cast<const float4*>(&X[gm * NFEAT + kc + xcol4 * 4]);
        float4 wv = *reinterpret_cast<const float4*>(&W[(kc + wrow) * NHID + wcol4 * 4]);

        __syncthreads();
        {   // duplicated stores of X: 4 x STS.64 of (a,a)
            unsigned long long* xrowp =
                reinterpret_cast<unsigned long long*>(&Xd[xrow][0]);
            xrowp[xcol4 * 4 + 0] = pack2(xv.x);
            xrowp[xcol4 * 4 + 1] = pack2(xv.y);
            xrowp[xcol4 * 4 + 2] = pack2(xv.z);
            xrowp[xcol4 * 4 + 3] = pack2(xv.w);
        }
        *reinterpret_cast<float4*>(&Ws[wrow][wcol4 * 4]) = wv;
        __syncthreads();

#pragma unroll
        for (int k = 0; k < 16; k++) {
            unsigned long long a0 =
                *reinterpret_cast<const unsigned long long*>(&Xd[ty * 4 + 0][2 * k]);
            unsigned long long a1 =
                *reinterpret_cast<const unsigned long long*>(&Xd[ty * 4 + 1][2 * k]);
            unsigned long long a2 =
                *reinterpret_cast<const unsigned long long*>(&Xd[ty * 4 + 2][2 * k]);
            unsigned long long a3 =
                *reinterpret_cast<const unsigned long long*>(&Xd[ty * 4 + 3][2 * k]);
            ulonglong2 b =
                *reinterpret_cast<const ulonglong2*>(&Ws[k][tx * 4]);
            fma2(acc[0][0], a0, b.x); fma2(acc[0][1], a0, b.y);
            fma2(acc[1][0], a1, b.x); fma2(acc[1][1], a1, b.y);
            fma2(acc[2][0], a2, b.x); fma2(acc[2][1], a2, b.y);
            fma2(acc[3][0], a3, b.x); fma2(acc[3][1], a3, b.y);
        }
    }

#pragma unroll
    for (int i = 0; i < 4; i++) {
        int m = m0 + ty * 4 + i;
        if (m < N_NODES) {
            float2 c0 = unpack2(acc[i][0]);
            float2 c1 = unpack2(acc[i][1]);
            *reinterpret_cast<float4*>(&g_h1[m * NHID + tx * 4]) =
                make_float4(c0.x, c0.y, c1.x, c1.y);
        }
    }
}

// ---------------------------------------------------------------------------
// scatter1: agg1[dst] += w * h1[src]    (64 floats/edge, 16 threads x float4)
// red.global.add.v4.f32 = 16B vector reduction (sm_90+).
// ---------------------------------------------------------------------------
__global__ __launch_bounds__(256) void scatter1_kernel(const int* __restrict__ ei,
                                                       const float* __restrict__ ew) {
    int gid = blockIdx.x * blockDim.x + threadIdx.x;
    int e = gid >> 4;
    int c = gid & 15;
    if (e >= N_EDGES) return;
    int s = ei[e];
    int d = ei[N_EDGES + e];
    float w = ew[e];
    float4 v = *reinterpret_cast<const float4*>(&g_h1[s * NHID + c * 4]);
    v.x *= w; v.y *= w; v.z *= w; v.w *= w;
    float* dst = &g_agg1[d * NHID + c * 4];
    asm volatile("red.global.add.v4.f32 [%0], {%1, %2, %3, %4};"
                 :: "l"(dst), "f"(v.x), "f"(v.y), "f"(v.z), "f"(v.w)
                 : "memory");
}

// ---------------------------------------------------------------------------
// GEMM2 (+fused ReLU): g_h2[100000,16] = relu(g_agg1)[100000,64] @ W2[64,16]
// ONE thread per node: agg1 row read exactly once, 16 outputs in registers
// (8 f32x2 accumulators).
// ---------------------------------------------------------------------------
__global__ __launch_bounds__(256) void gemm2_kernel(const float* __restrict__ W2) {
    __shared__ float Ws[NHID * NCLASS];  // [64][16] row-major, 1024 floats
    const int tid = threadIdx.x;
    reinterpret_cast<float4*>(Ws)[tid] = reinterpret_cast<const float4*>(W2)[tid];
    __syncthreads();

    int node = blockIdx.x * blockDim.x + tid;
    if (node >= N_NODES) return;

    unsigned long long acc[8] = {};      // 16 output cols as 8 pairs

#pragma unroll
    for (int k4 = 0; k4 < NHID / 4; k4++) {
        float4 a = *reinterpret_cast<const float4*>(&g_agg1[node * NHID + k4 * 4]);
        a.x = fmaxf(a.x, 0.f); a.y = fmaxf(a.y, 0.f);
        a.z = fmaxf(a.z, 0.f); a.w = fmaxf(a.w, 0.f);
#pragma unroll
        for (int j = 0; j < 4; j++) {
            float av = (j == 0) ? a.x : (j == 1) ? a.y : (j == 2) ? a.z : a.w;
            unsigned long long ap = pack2(av);
            const ulonglong2* wr = reinterpret_cast<const ulonglong2*>(
                &Ws[(k4 * 4 + j) * NCLASS]);
            ulonglong2 w01 = wr[0];
            ulonglong2 w23 = wr[1];
            ulonglong2 w45 = wr[2];
            ulonglong2 w67 = wr[3];
            fma2(acc[0], ap, w01.x); fma2(acc[1], ap, w01.y);
            fma2(acc[2], ap, w23.x); fma2(acc[3], ap, w23.y);
            fma2(acc[4], ap, w45.x); fma2(acc[5], ap, w45.y);
            fma2(acc[6], ap, w67.x); fma2(acc[7], ap, w67.y);
        }
    }

#pragma unroll
    for (int p = 0; p < 4; p++) {
        float2 lo = unpack2(acc[p * 2 + 0]);
        float2 hi = unpack2(acc[p * 2 + 1]);
        *reinterpret_cast<float4*>(&g_h2[node * NCLASS + p * 4]) =
            make_float4(lo.x, lo.y, hi.x, hi.y);
    }
}

// ---------------------------------------------------------------------------
// scatter2: out[dst] += w * h2[src]    (16 floats/edge, 4 threads x float4)
// ---------------------------------------------------------------------------
__global__ __launch_bounds__(256) void scatter2_kernel(const int* __restrict__ ei,
                                                       const float* __restrict__ ew,
                                                       float* __restrict__ out) {
    int gid = blockIdx.x * blockDim.x + threadIdx.x;
    int e = gid >> 2;
    int c = gid & 3;
    if (e >= N_EDGES) return;
    int s = ei[e];
    int d = ei[N_EDGES + e];
    float w = ew[e];
    float4 v = *reinterpret_cast<const float4*>(&g_h2[s * NCLASS + c * 4]);
    v.x *= w; v.y *= w; v.z *= w; v.w *= w;
    float* dst = &out[d * NCLASS + c * 4];
    asm volatile("red.global.add.v4.f32 [%0], {%1, %2, %3, %4};"
                 :: "l"(dst), "f"(v.x), "f"(v.y), "f"(v.z), "f"(v.w)
                 : "memory");
}

// ---------------------------------------------------------------------------
extern "C" void kernel_launch(void* const* d_in, const int* in_sizes, int n_in,
                              void* d_out, int out_size) {
    const float* x   = (const float*)d_in[0];
    const int*   ei1 = (const int*)  d_in[1];
    const int*   ei2 = (const int*)  d_in[2];
    const float* ew1 = (const float*)d_in[3];
    const float* ew2 = (const float*)d_in[4];
    const float* W1  = (const float*)d_in[5];
    const float* W2  = (const float*)d_in[6];
    float* out = (float*)d_out;

    zero_kernel<<<2048, 256>>>(out);
    gemm1_kernel<<<(N_NODES + 63) / 64, 256>>>(x, W1);
    scatter1_kernel<<<(N_EDGES * 16 + 255) / 256, 256>>>(ei1, ew1);
    gemm2_kernel<<<(N_NODES + 255) / 256, 256>>>(W2);
    scatter2_kernel<<<(N_EDGES * 4 + 255) / 256, 256>>>(ei2, ew2, out);
}

// round 4
// speedup vs baseline: 1.1100x; 1.1100x over previous
#include <cuda_runtime.h>
#include <cstdint>

#define N_NODES 100000
#define N_EDGES 1600000
#define NFEAT   128
#define NHID    64
#define NCLASS  16

// Scratch (device globals — no allocation allowed in kernel_launch)
__device__ float g_h1[N_NODES * NHID];     // X @ W1
__device__ float g_agg1[N_NODES * NHID];   // scatter1 accumulator
__device__ float g_h2[N_NODES * NCLASS];   // relu(agg1) @ W2

// ---------------- f32x2 packed helpers (SASS FFMA2 — only via PTX) ----------
__device__ __forceinline__ void fma2(unsigned long long& d,
                                     unsigned long long a,
                                     unsigned long long b) {
    asm("fma.rn.f32x2 %0, %1, %2, %3;" : "=l"(d) : "l"(a), "l"(b), "l"(d));
}
__device__ __forceinline__ unsigned long long add2(unsigned long long a,
                                                   unsigned long long b) {
    unsigned long long r;
    asm("add.rn.f32x2 %0, %1, %2;" : "=l"(r) : "l"(a), "l"(b));
    return r;
}
__device__ __forceinline__ unsigned long long pack2(float a) {
    unsigned long long r;
    asm("mov.b64 %0, {%1, %1};" : "=l"(r) : "f"(a));
    return r;
}
__device__ __forceinline__ float2 unpack2(unsigned long long p) {
    float2 f;
    asm("mov.b64 {%0, %1}, %2;" : "=f"(f.x), "=f"(f.y) : "l"(p));
    return f;
}
__device__ __forceinline__ uint32_t f2tf32(float f) {
    uint32_t r;
    asm("cvt.rna.tf32.f32 %0, %1;" : "=r"(r) : "f"(f));
    return r;
}

// ---------------------------------------------------------------------------
// Zero agg1 and d_out (atomically accumulated; must start at 0 every launch).
// ---------------------------------------------------------------------------
__global__ void zero_kernel(float* __restrict__ out) {
    const int stride = gridDim.x * blockDim.x;
    int i = blockIdx.x * blockDim.x + threadIdx.x;
    const float4 z = make_float4(0.f, 0.f, 0.f, 0.f);
    const int n1 = N_NODES * NHID / 4;
    const int n2 = N_NODES * NCLASS / 4;
    for (int idx = i; idx < n1; idx += stride)
        reinterpret_cast<float4*>(g_agg1)[idx] = z;
    for (int idx = i; idx < n2; idx += stride)
        reinterpret_cast<float4*>(out)[idx] = z;
}

// ---------------------------------------------------------------------------
// GEMM1 (tf32 tensor cores): g_h1[100000,64] = X[100000,128] @ W1[128,64]
// Block: 256 threads = 8 warps, tile 128(M) x 64(N), K chunks of 32.
// Warp grid: 4 (M, 32 rows each) x 2 (N, 32 cols each).
// mma.sync.aligned.m16n8k8.row.col.f32.tf32.tf32.f32
// Operands converted to tf32 (cvt.rna) during smem staging.
// ---------------------------------------------------------------------------
__global__ __launch_bounds__(256) void gemm1_kernel(const float* __restrict__ X,
                                                    const float* __restrict__ W) {
    __shared__ float Xs[128][36];   // 128 rows x 32 k (+4 pad) : 18 KB
    __shared__ float Ws[32][72];    // 32 k x 64 n (+8 pad, conflict-free frags)

    const int tid  = threadIdx.x;
    const int lane = tid & 31;
    const int warp = tid >> 5;
    const int m0   = blockIdx.x * 128;
    const int wm   = warp >> 1;        // 0..3 -> rows wm*32
    const int wn   = warp & 1;         // 0..1 -> cols wn*32
    const int gr   = lane >> 2;        // group row 0..7
    const int tg   = lane & 3;         // thread-in-group 0..3

    float acc[2][4][4];
#pragma unroll
    for (int mi = 0; mi < 2; mi++)
#pragma unroll
        for (int ni = 0; ni < 4; ni++)
#pragma unroll
            for (int r = 0; r < 4; r++) acc[mi][ni][r] = 0.f;

    for (int kc = 0; kc < NFEAT; kc += 32) {
        __syncthreads();
        // stage X chunk: 128x32 floats = 1024 float4, 4 per thread
#pragma unroll
        for (int t = 0; t < 4; t++) {
            int f4  = tid + t * 256;
            int row = f4 >> 3;
            int c4  = (f4 & 7) * 4;
            int gm  = m0 + row;
            float4 v = make_float4(0.f, 0.f, 0.f, 0.f);
            if (gm < N_NODES)
                v = *reinterpret_cast<const float4*>(&X[gm * NFEAT + kc + c4]);
            Xs[row][c4 + 0] = __uint_as_float(f2tf32(v.x));
            Xs[row][c4 + 1] = __uint_as_float(f2tf32(v.y));
            Xs[row][c4 + 2] = __uint_as_float(f2tf32(v.z));
            Xs[row][c4 + 3] = __uint_as_float(f2tf32(v.w));
        }
        // stage W chunk: 32x64 floats = 512 float4, 2 per thread
#pragma unroll
        for (int t = 0; t < 2; t++) {
            int f4  = tid + t * 256;
            int row = f4 >> 4;
            int c4  = (f4 & 15) * 4;
            float4 v = *reinterpret_cast<const float4*>(&W[(kc + row) * NHID + c4]);
            Ws[row][c4 + 0] = __uint_as_float(f2tf32(v.x));
            Ws[row][c4 + 1] = __uint_as_float(f2tf32(v.y));
            Ws[row][c4 + 2] = __uint_as_float(f2tf32(v.z));
            Ws[row][c4 + 3] = __uint_as_float(f2tf32(v.w));
        }
        __syncthreads();

#pragma unroll
        for (int ks = 0; ks < 32; ks += 8) {
            uint32_t a[2][4];
#pragma unroll
            for (int mi = 0; mi < 2; mi++) {
                int base = wm * 32 + mi * 16;
                a[mi][0] = __float_as_uint(Xs[base + gr][ks + tg]);
                a[mi][1] = __float_as_uint(Xs[base + gr + 8][ks + tg]);
                a[mi][2] = __float_as_uint(Xs[base + gr][ks + tg + 4]);
                a[mi][3] = __float_as_uint(Xs[base + gr + 8][ks + tg + 4]);
            }
#pragma unroll
            for (int ni = 0; ni < 4; ni++) {
                int cb = wn * 32 + ni * 8;
                uint32_t b0 = __float_as_uint(Ws[ks + tg][cb + gr]);
                uint32_t b1 = __float_as_uint(Ws[ks + tg + 4][cb + gr]);
#pragma unroll
                for (int mi = 0; mi < 2; mi++) {
                    asm volatile(
                        "mma.sync.aligned.m16n8k8.row.col.f32.tf32.tf32.f32 "
                        "{%0,%1,%2,%3}, {%4,%5,%6,%7}, {%8,%9}, {%0,%1,%2,%3};"
                        : "+f"(acc[mi][ni][0]), "+f"(acc[mi][ni][1]),
                          "+f"(acc[mi][ni][2]), "+f"(acc[mi][ni][3])
                        : "r"(a[mi][0]), "r"(a[mi][1]), "r"(a[mi][2]), "r"(a[mi][3]),
                          "r"(b0), "r"(b1));
                }
            }
        }
    }

    // epilogue: c0,c1 at (row, 2tg), c2,c3 at (row+8, 2tg)
#pragma unroll
    for (int mi = 0; mi < 2; mi++) {
#pragma unroll
        for (int ni = 0; ni < 4; ni++) {
            int row = m0 + wm * 32 + mi * 16 + gr;
            int col = wn * 32 + ni * 8 + tg * 2;
            if (row < N_NODES)
                *reinterpret_cast<float2*>(&g_h1[row * NHID + col]) =
                    make_float2(acc[mi][ni][0], acc[mi][ni][1]);
            if (row + 8 < N_NODES)
                *reinterpret_cast<float2*>(&g_h1[(row + 8) * NHID + col]) =
                    make_float2(acc[mi][ni][2], acc[mi][ni][3]);
        }
    }
}

// ---------------------------------------------------------------------------
// scatter1: agg1[dst] += w * h1[src]    (64 floats/edge, 16 threads x float4)
// ---------------------------------------------------------------------------
__global__ __launch_bounds__(256) void scatter1_kernel(const int* __restrict__ ei,
                                                       const float* __restrict__ ew) {
    int gid = blockIdx.x * blockDim.x + threadIdx.x;
    int e = gid >> 4;
    int c = gid & 15;
    if (e >= N_EDGES) return;
    int s = ei[e];
    int d = ei[N_EDGES + e];
    float w = ew[e];
    float4 v = *reinterpret_cast<const float4*>(&g_h1[s * NHID + c * 4]);
    v.x *= w; v.y *= w; v.z *= w; v.w *= w;
    float* dst = &g_agg1[d * NHID + c * 4];
    asm volatile("red.global.add.v4.f32 [%0], {%1, %2, %3, %4};"
                 :: "l"(dst), "f"(v.x), "f"(v.y), "f"(v.z), "f"(v.w)
                 : "memory");
}

// ---------------------------------------------------------------------------
// GEMM2 (+fused ReLU): g_h2[100000,16] = relu(g_agg1)[100000,64] @ W2[64,16]
// 4-way split-K: 4 threads per node (h = lane>>3 owns 16 hid values), row
// read exactly once; partials combined via butterfly shfl_xor(8), shfl_xor(16).
// Lane mapping: nsub = lane&7 (node), h = lane>>3 — all 4 partials of a node
// live in one warp.
// ---------------------------------------------------------------------------
__global__ __launch_bounds__(256) void gemm2_kernel(const float* __restrict__ W2) {
    __shared__ float Ws[NHID * NCLASS];  // [64][16] row-major, 1024 floats
    const int tid = threadIdx.x;
    reinterpret_cast<float4*>(Ws)[tid] = reinterpret_cast<const float4*>(W2)[tid];
    __syncthreads();

    const int lane = tid & 31;
    const int nsub = lane & 7;
    const int h    = lane >> 3;            // k-quarter: hid [h*16, h*16+16)
    const int node = blockIdx.x * 64 + (tid >> 5) * 8 + nsub;
    const bool valid = (node < N_NODES);
    const int nclamp = valid ? node : 0;

    unsigned long long acc[8] = {};        // 16 output cols as 8 f32x2 pairs

    const float* arow = &g_agg1[nclamp * NHID + h * 16];
#pragma unroll
    for (int k4 = 0; k4 < 4; k4++) {
        float4 a = *reinterpret_cast<const float4*>(&arow[k4 * 4]);
        if (!valid) a = make_float4(0.f, 0.f, 0.f, 0.f);
        a.x = fmaxf(a.x, 0.f); a.y = fmaxf(a.y, 0.f);
        a.z = fmaxf(a.z, 0.f); a.w = fmaxf(a.w, 0.f);
#pragma unroll
        for (int j = 0; j < 4; j++) {
            float av = (j == 0) ? a.x : (j == 1) ? a.y : (j == 2) ? a.z : a.w;
            unsigned long long ap = pack2(av);
            const ulonglong2* wr = reinterpret_cast<const ulonglong2*>(
                &Ws[(h * 16 + k4 * 4 + j) * NCLASS]);
            ulonglong2 w01 = wr[0];
            ulonglong2 w23 = wr[1];
            ulonglong2 w45 = wr[2];
            ulonglong2 w67 = wr[3];
            fma2(acc[0], ap, w01.x); fma2(acc[1], ap, w01.y);
            fma2(acc[2], ap, w23.x); fma2(acc[3], ap, w23.y);
            fma2(acc[4], ap, w45.x); fma2(acc[5], ap, w45.y);
            fma2(acc[6], ap, w67.x); fma2(acc[7], ap, w67.y);
        }
    }

    // combine the 4 k-quarter partials (lanes nsub, nsub+8, nsub+16, nsub+24)
#pragma unroll
    for (int p = 0; p < 8; p++) {
        acc[p] = add2(acc[p], __shfl_xor_sync(0xffffffffu, acc[p], 8));
        acc[p] = add2(acc[p], __shfl_xor_sync(0xffffffffu, acc[p], 16));
    }

    // each lane writes its h-quarter of the 16 outputs: cols [h*4, h*4+4)
    if (valid) {
        float2 lo = unpack2(acc[2 * h + 0]);
        float2 hi = unpack2(acc[2 * h + 1]);
        *reinterpret_cast<float4*>(&g_h2[node * NCLASS + h * 4]) =
            make_float4(lo.x, lo.y, hi.x, hi.y);
    }
}

// ---------------------------------------------------------------------------
// scatter2: out[dst] += w * h2[src]    (16 floats/edge, 4 threads x float4)
// ---------------------------------------------------------------------------
__global__ __launch_bounds__(256) void scatter2_kernel(const int* __restrict__ ei,
                                                       const float* __restrict__ ew,
                                                       float* __restrict__ out) {
    int gid = blockIdx.x * blockDim.x + threadIdx.x;
    int e = gid >> 2;
    int c = gid & 3;
    if (e >= N_EDGES) return;
    int s = ei[e];
    int d = ei[N_EDGES + e];
    float w = ew[e];
    float4 v = *reinterpret_cast<const float4*>(&g_h2[s * NCLASS + c * 4]);
    v.x *= w; v.y *= w; v.z *= w; v.w *= w;
    float* dst = &out[d * NCLASS + c * 4];
    asm volatile("red.global.add.v4.f32 [%0], {%1, %2, %3, %4};"
                 :: "l"(dst), "f"(v.x), "f"(v.y), "f"(v.z), "f"(v.w)
                 : "memory");
}

// ---------------------------------------------------------------------------
extern "C" void kernel_launch(void* const* d_in, const int* in_sizes, int n_in,
                              void* d_out, int out_size) {
    const float* x   = (const float*)d_in[0];
    const int*   ei1 = (const int*)  d_in[1];
    const int*   ei2 = (const int*)  d_in[2];
    const float* ew1 = (const float*)d_in[3];
    const float* ew2 = (const float*)d_in[4];
    const float* W1  = (const float*)d_in[5];
    const float* W2  = (const float*)d_in[6];
    float* out = (float*)d_out;

    zero_kernel<<<2048, 256>>>(out);
    gemm1_kernel<<<(N_NODES + 127) / 128, 256>>>(x, W1);
    scatter1_kernel<<<(N_EDGES * 16 + 255) / 256, 256>>>(ei1, ew1);
    gemm2_kernel<<<(N_NODES + 63) / 64, 256>>>(W2);
    scatter2_kernel<<<(N_EDGES * 4 + 255) / 256, 256>>>(ei2, ew2, out);
}